// round 13
// baseline (speedup 1.0000x reference)
#include <cuda_runtime.h>
#include <math.h>
#include <stdint.h>

// Problem: B=2, N=2048, C=1024, H=16, D=64, SCALE=1/8
#define M_ROWS 4096
#define QKV_N  3072
#define CC     1024

// Scratch (device globals: allocation-guard-safe)
__device__ float g_qkv[4096 * 3072];     // [B*N, 3C] tf32-rounded, q pre-scaled
__device__ float g_att[4096 * 1024];     // [B*N, C] tf32-rounded
__device__ float g_xr[4096 * 1024];      // tf32-rounded x
__device__ float g_wqkvr[1024 * 3072];   // tf32-rounded w_qkv
__device__ float g_wprojr[1024 * 1024];  // tf32-rounded w_proj

// ---------------------------------------------------------------------------
// helpers
// ---------------------------------------------------------------------------
__device__ __forceinline__ uint32_t f2tf(float f) {
    uint32_t u;
    asm("cvt.rna.tf32.f32 %0, %1;" : "=r"(u) : "f"(f));
    return u;
}
__device__ __forceinline__ float rtf(float f) { return __uint_as_float(f2tf(f)); }
__device__ __forceinline__ uint32_t fbits(float f) { return __float_as_uint(f); }

__device__ __forceinline__ void mma8(float* d, const uint32_t* a, const uint32_t* b) {
    asm volatile(
        "mma.sync.aligned.m16n8k8.row.col.f32.tf32.tf32.f32 "
        "{%0,%1,%2,%3}, {%4,%5,%6,%7}, {%8,%9}, {%0,%1,%2,%3};"
        : "+f"(d[0]), "+f"(d[1]), "+f"(d[2]), "+f"(d[3])
        : "r"(a[0]), "r"(a[1]), "r"(a[2]), "r"(a[3]), "r"(b[0]), "r"(b[1]));
}

__device__ __forceinline__ uint32_t smaddr(const void* p) {
    return (uint32_t)__cvta_generic_to_shared(p);
}
#define CP16(dst, src) \
    asm volatile("cp.async.cg.shared.global [%0], [%1], 16;" :: "r"(dst), "l"(src))
#define CP_COMMIT() asm volatile("cp.async.commit_group;")
#define CP_WAIT(n)  asm volatile("cp.async.wait_group %0;" :: "n"(n))

// ---------------------------------------------------------------------------
// Pre-pass: round fp32 -> tf32-valid fp32
// ---------------------------------------------------------------------------
__global__ void round_kernel(const float4* __restrict__ src, float4* __restrict__ dst, int n4) {
    int i = blockIdx.x * blockDim.x + threadIdx.x;
    if (i < n4) {
        float4 t = src[i];
        t.x = rtf(t.x); t.y = rtf(t.y); t.z = rtf(t.z); t.w = rtf(t.w);
        dst[i] = t;
    }
}

// ---------------------------------------------------------------------------
// TF32 GEMM, 3-stage cp.async pipeline, ONE barrier per K-slab.
// BM=BN=128, BK=32, 256 thr (8 warps 2m x 4n), warp tile 64x32.
// As[m][36] (bank = 4*l2+l4 pattern, conflict-free), Bs[k][136].
// ---------------------------------------------------------------------------
struct GemmSmem {
    float As[3][128][36];
    float Bs[3][32][136];
};
#define GEMM_SMEM ((int)sizeof(GemmSmem))

template <bool HAS_BIAS, bool ROUND_OUT, bool SCALE_Q>
__global__ __launch_bounds__(256, 2) void gemm_tf32(
    const float* __restrict__ A, const float* __restrict__ B,
    const float* __restrict__ bias, float* __restrict__ C,
    int M, int N, int K)
{
    extern __shared__ uint8_t smraw[];
    GemmSmem& S = *reinterpret_cast<GemmSmem*>(smraw);

    const int tid = threadIdx.x, lane = tid & 31, wid = tid >> 5;
    const int l4 = lane & 3, l2 = lane >> 2;
    const int wm = (wid & 1) * 64, wn = (wid >> 1) * 32;
    const int rowBase = blockIdx.y * 128, colBase = blockIdx.x * 128;

    const float* Ag = A + (size_t)rowBase * K;
    const float* Bg = B + colBase;

    float acc[4][4][4];
#pragma unroll
    for (int mt = 0; mt < 4; mt++)
#pragma unroll
        for (int nt = 0; nt < 4; nt++)
#pragma unroll
            for (int i = 0; i < 4; i++) acc[mt][nt][i] = 0.f;

    auto issue = [&](int s, int k0) {
#pragma unroll
        for (int i = 0; i < 4; i++) {              // A tile 128x32
            int c = tid + 256 * i;
            int row = c >> 3, cc = (c & 7) << 2;
            CP16(smaddr(&S.As[s][row][cc]), Ag + (size_t)row * K + k0 + cc);
        }
#pragma unroll
        for (int i = 0; i < 4; i++) {              // B tile 32x128
            int c = tid + 256 * i;
            int kr = c >> 5, nc = (c & 31) << 2;
            CP16(smaddr(&S.Bs[s][kr][nc]), Bg + (size_t)(k0 + kr) * N + nc);
        }
        CP_COMMIT();
    };

    const int nIter = K >> 5;
    issue(0, 0);
    if (nIter > 1) issue(1, 32);

    for (int it = 0; it < nIter; it++) {
        if (it + 1 < nIter) { CP_WAIT(1); } else { CP_WAIT(0); }
        __syncthreads();               // slab `it` visible; compute of it-1 done
        if (it + 2 < nIter) issue((it + 2) % 3, (it + 2) << 5);
        const int buf = it % 3;

#pragma unroll
        for (int ks = 0; ks < 32; ks += 8) {
            uint32_t af[4][4], bf[4][2];
#pragma unroll
            for (int mt = 0; mt < 4; mt++) {
                int r = wm + mt * 16 + l2;
                af[mt][0] = fbits(S.As[buf][r][ks + l4]);
                af[mt][1] = fbits(S.As[buf][r + 8][ks + l4]);
                af[mt][2] = fbits(S.As[buf][r][ks + l4 + 4]);
                af[mt][3] = fbits(S.As[buf][r + 8][ks + l4 + 4]);
            }
#pragma unroll
            for (int nt = 0; nt < 4; nt++) {
                int c = wn + nt * 8 + l2;
                bf[nt][0] = fbits(S.Bs[buf][ks + l4][c]);
                bf[nt][1] = fbits(S.Bs[buf][ks + l4 + 4][c]);
            }
#pragma unroll
            for (int mt = 0; mt < 4; mt++)
#pragma unroll
                for (int nt = 0; nt < 4; nt++)
                    mma8(acc[mt][nt], af[mt], bf[nt]);
        }
    }

#pragma unroll
    for (int mt = 0; mt < 4; mt++) {
        int row = rowBase + wm + mt * 16 + l2;
#pragma unroll
        for (int nt = 0; nt < 4; nt++) {
            int col = colBase + wn + nt * 8 + 2 * l4;
            float sc = 1.f;
            if (SCALE_Q) sc = (col < 1024) ? 0.125f : 1.f;
            float bx = 0.f, by = 0.f;
            if (HAS_BIAS) { bx = bias[col]; by = bias[col + 1]; }
            float2 v0, v1;
            v0.x = acc[mt][nt][0] * sc + bx;  v0.y = acc[mt][nt][1] * sc + by;
            v1.x = acc[mt][nt][2] * sc + bx;  v1.y = acc[mt][nt][3] * sc + by;
            if (ROUND_OUT) {
                v0.x = rtf(v0.x); v0.y = rtf(v0.y);
                v1.x = rtf(v1.x); v1.y = rtf(v1.y);
            }
            *(float2*)(C + (size_t)row * N + col) = v0;
            *(float2*)(C + (size_t)(row + 8) * N + col) = v1;
        }
    }
}

// ---------------------------------------------------------------------------
// Flash attention, tf32 mma, 3-stage cp.async K/V, one barrier per kv-tile.
// Block = (q-tile 128, (b,h)). 8 warps x 16 q-rows, full kv width (64).
// ---------------------------------------------------------------------------
struct FlashSmem {
    float Qs[128][68];
    float Ks[3][64][68];
    float Vs[3][64][72];
    float Ps[128][68];
};
#define FLASH_SMEM ((int)sizeof(FlashSmem))

__global__ __launch_bounds__(256, 1) void flash_tf32()
{
    extern __shared__ uint8_t smraw[];
    FlashSmem& S = *reinterpret_cast<FlashSmem*>(smraw);

    const int tid = threadIdx.x, lane = tid & 31, wid = tid >> 5;
    const int l4 = lane & 3, l2 = lane >> 2;
    const int qt = blockIdx.x;            // 0..15
    const int bh = blockIdx.y;            // 0..31
    const int b = bh >> 4, h = bh & 15;
    const int rowb = wid * 16;

    const float* Qg = g_qkv + (size_t)b * 2048 * 3072 + (size_t)h * 64;
    const float* Kg = Qg + 1024;
    const float* Vg = Qg + 2048;

    auto issueKV = [&](int s, int kt) {
#pragma unroll
        for (int i = 0; i < 4; i++) {
            int c = tid + 256 * i;
            int r = c >> 4, cc = (c & 15) << 2;
            CP16(smaddr(&S.Ks[s][r][cc]), Kg + (size_t)(kt * 64 + r) * 3072 + cc);
        }
#pragma unroll
        for (int i = 0; i < 4; i++) {
            int c = tid + 256 * i;
            int r = c >> 4, cc = (c & 15) << 2;
            CP16(smaddr(&S.Vs[s][r][cc]), Vg + (size_t)(kt * 64 + r) * 3072 + cc);
        }
        CP_COMMIT();
    };

    // prologue: Q + KV0 in group 0; KV1 in group 1
#pragma unroll
    for (int i = 0; i < 8; i++) {
        int c = tid + 256 * i;
        int r = c >> 4, cc = (c & 15) << 2;
        CP16(smaddr(&S.Qs[r][cc]), Qg + (size_t)(qt * 128 + r) * 3072 + cc);
    }
    issueKV(0, 0);
    issueKV(1, 1);

    float o[8][4];
    float m[2] = {-1e30f, -1e30f}, l[2] = {0.f, 0.f};
#pragma unroll
    for (int nt = 0; nt < 8; nt++)
#pragma unroll
        for (int i = 0; i < 4; i++) o[nt][i] = 0.f;

    for (int kt = 0; kt < 32; kt++) {
        if (kt + 1 < 32) { CP_WAIT(1); } else { CP_WAIT(0); }
        __syncthreads();               // KV tile kt visible; compute kt-1 done
        if (kt + 2 < 32) issueKV((kt + 2) % 3, kt + 2);
        const int buf = kt % 3;

        // S = Q @ K^T  (16 x 64 per warp, k=64). Q pre-scaled by 1/8.
        float s[8][4];
#pragma unroll
        for (int nt = 0; nt < 8; nt++)
#pragma unroll
            for (int i = 0; i < 4; i++) s[nt][i] = 0.f;
#pragma unroll
        for (int ks = 0; ks < 64; ks += 8) {
            uint32_t a[4];
            a[0] = fbits(S.Qs[rowb + l2][ks + l4]);
            a[1] = fbits(S.Qs[rowb + l2 + 8][ks + l4]);
            a[2] = fbits(S.Qs[rowb + l2][ks + l4 + 4]);
            a[3] = fbits(S.Qs[rowb + l2 + 8][ks + l4 + 4]);
#pragma unroll
            for (int nt = 0; nt < 8; nt++) {
                uint32_t bfr[2] = {fbits(S.Ks[buf][nt * 8 + l2][ks + l4]),
                                   fbits(S.Ks[buf][nt * 8 + l2][ks + l4 + 4])};
                mma8(s[nt], a, bfr);
            }
        }

        // online softmax (width-4 shuffle segments; rows rr: regs 2rr, 2rr+1)
#pragma unroll
        for (int rr = 0; rr < 2; rr++) {
            float mloc = -1e30f;
#pragma unroll
            for (int nt = 0; nt < 8; nt++)
                mloc = fmaxf(mloc, fmaxf(s[nt][2 * rr], s[nt][2 * rr + 1]));
            mloc = fmaxf(mloc, __shfl_xor_sync(0xffffffffu, mloc, 1, 4));
            mloc = fmaxf(mloc, __shfl_xor_sync(0xffffffffu, mloc, 2, 4));
            float mn = fmaxf(m[rr], mloc);
            float fac = __expf(m[rr] - mn);
            m[rr] = mn;
            float lloc = 0.f;
#pragma unroll
            for (int nt = 0; nt < 8; nt++) {
                s[nt][2 * rr]     = __expf(s[nt][2 * rr] - mn);
                s[nt][2 * rr + 1] = __expf(s[nt][2 * rr + 1] - mn);
                lloc += s[nt][2 * rr] + s[nt][2 * rr + 1];
            }
            lloc += __shfl_xor_sync(0xffffffffu, lloc, 1, 4);
            lloc += __shfl_xor_sync(0xffffffffu, lloc, 2, 4);
            l[rr] = l[rr] * fac + lloc;
#pragma unroll
            for (int nt = 0; nt < 8; nt++) {
                o[nt][2 * rr]     *= fac;
                o[nt][2 * rr + 1] *= fac;
            }
        }

        // P -> smem (tf32-rounded), warp-private rows
#pragma unroll
        for (int nt = 0; nt < 8; nt++) {
            int col = nt * 8 + 2 * l4;
            float2 p0 = make_float2(rtf(s[nt][0]), rtf(s[nt][1]));
            *(float2*)&S.Ps[rowb + l2][col] = p0;
            float2 p1 = make_float2(rtf(s[nt][2]), rtf(s[nt][3]));
            *(float2*)&S.Ps[rowb + l2 + 8][col] = p1;
        }
        __syncwarp();

        // O += P @ V
#pragma unroll
        for (int ks = 0; ks < 64; ks += 8) {
            uint32_t a[4];
            a[0] = fbits(S.Ps[rowb + l2][ks + l4]);
            a[1] = fbits(S.Ps[rowb + l2 + 8][ks + l4]);
            a[2] = fbits(S.Ps[rowb + l2][ks + l4 + 4]);
            a[3] = fbits(S.Ps[rowb + l2 + 8][ks + l4 + 4]);
#pragma unroll
            for (int nt = 0; nt < 8; nt++) {
                uint32_t bfr[2] = {fbits(S.Vs[buf][ks + l4][nt * 8 + l2]),
                                   fbits(S.Vs[buf][ks + l4 + 4][nt * 8 + l2])};
                mma8(o[nt], a, bfr);
            }
        }
    }

    // epilogue (rounded so the proj GEMM consumes tf32-valid data)
    const float inv0 = 1.f / l[0], inv1 = 1.f / l[1];
    float* Og = g_att + ((size_t)b * 2048 + (size_t)qt * 128) * 1024 + (size_t)h * 64;
    const int r0 = rowb + l2;
#pragma unroll
    for (int nt = 0; nt < 8; nt++) {
        int col = nt * 8 + 2 * l4;
        float2 v0 = make_float2(rtf(o[nt][0] * inv0), rtf(o[nt][1] * inv0));
        *(float2*)(Og + (size_t)r0 * 1024 + col) = v0;
        float2 v1 = make_float2(rtf(o[nt][2] * inv1), rtf(o[nt][3] * inv1));
        *(float2*)(Og + (size_t)(r0 + 8) * 1024 + col) = v1;
    }
}

// ---------------------------------------------------------------------------
extern "C" void kernel_launch(void* const* d_in, const int* in_sizes, int n_in,
                              void* d_out, int out_size)
{
    const float* x      = (const float*)d_in[0];   // [2,2048,1024]
    const float* w_qkv  = (const float*)d_in[1];   // [1024,3072]
    const float* w_proj = (const float*)d_in[2];   // [1024,1024]
    const float* b_proj = (const float*)d_in[3];   // [1024]
    float* out = (float*)d_out;                    // [2,2048,1024]

    float *qkv, *att, *xr, *wqkvr, *wprojr;
    cudaGetSymbolAddress((void**)&qkv, g_qkv);
    cudaGetSymbolAddress((void**)&att, g_att);
    cudaGetSymbolAddress((void**)&xr, g_xr);
    cudaGetSymbolAddress((void**)&wqkvr, g_wqkvr);
    cudaGetSymbolAddress((void**)&wprojr, g_wprojr);

    // 0) pre-round inputs to the tf32 grid
    round_kernel<<<(4096 * 1024 / 4 + 255) / 256, 256>>>(
        (const float4*)x, (float4*)xr, 4096 * 1024 / 4);
    round_kernel<<<(1024 * 3072 / 4 + 255) / 256, 256>>>(
        (const float4*)w_qkv, (float4*)wqkvr, 1024 * 3072 / 4);
    round_kernel<<<(1024 * 1024 / 4 + 255) / 256, 256>>>(
        (const float4*)w_proj, (float4*)wprojr, 1024 * 1024 / 4);

    // 1) QKV projection (epilogue: q *= 1/8, round tf32)
    cudaFuncSetAttribute((const void*)gemm_tf32<false, true, true>,
                         cudaFuncAttributeMaxDynamicSharedMemorySize, GEMM_SMEM);
    gemm_tf32<false, true, true><<<dim3(QKV_N / 128, M_ROWS / 128), 256, GEMM_SMEM>>>(
        xr, wqkvr, nullptr, qkv, M_ROWS, QKV_N, CC);

    // 2) Flash attention
    cudaFuncSetAttribute(flash_tf32,
                         cudaFuncAttributeMaxDynamicSharedMemorySize, FLASH_SMEM);
    flash_tf32<<<dim3(16, 32), 256, FLASH_SMEM>>>();

    // 3) Output projection + bias (fp32 out)
    cudaFuncSetAttribute((const void*)gemm_tf32<true, false, false>,
                         cudaFuncAttributeMaxDynamicSharedMemorySize, GEMM_SMEM);
    gemm_tf32<true, false, false><<<dim3(CC / 128, M_ROWS / 128), 256, GEMM_SMEM>>>(
        att, wprojr, b_proj, out, M_ROWS, CC, CC);
}

// round 14
// speedup vs baseline: 1.1564x; 1.1564x over previous
#include <cuda_runtime.h>
#include <math.h>
#include <stdint.h>

// Problem: B=2, N=2048, C=1024, H=16, D=64, SCALE=1/8
#define M_ROWS 4096
#define QKV_N  3072
#define CC     1024

// Scratch (device globals: allocation-guard-safe)
__device__ float g_qkv[4096 * 3072];     // [B*N, 3C] tf32-rounded, q pre-scaled
__device__ float g_att[4096 * 1024];     // [B*N, C] tf32-rounded
__device__ float g_xr[4096 * 1024];      // tf32-rounded x
__device__ float g_wqkvT[3072 * 1024];   // rounded w_qkv^T  [N][K]
__device__ float g_wprojT[1024 * 1024];  // rounded w_proj^T [N][K]

// ---------------------------------------------------------------------------
// helpers
// ---------------------------------------------------------------------------
__device__ __forceinline__ uint32_t f2tf(float f) {
    uint32_t u;
    asm("cvt.rna.tf32.f32 %0, %1;" : "=r"(u) : "f"(f));
    return u;
}
__device__ __forceinline__ float rtf(float f) { return __uint_as_float(f2tf(f)); }
__device__ __forceinline__ uint32_t fbits(float f) { return __float_as_uint(f); }

__device__ __forceinline__ void mma8(float* d, const uint32_t* a, const uint32_t* b) {
    asm volatile(
        "mma.sync.aligned.m16n8k8.row.col.f32.tf32.tf32.f32 "
        "{%0,%1,%2,%3}, {%4,%5,%6,%7}, {%8,%9}, {%0,%1,%2,%3};"
        : "+f"(d[0]), "+f"(d[1]), "+f"(d[2]), "+f"(d[3])
        : "r"(a[0]), "r"(a[1]), "r"(a[2]), "r"(a[3]), "r"(b[0]), "r"(b[1]));
}

__device__ __forceinline__ uint32_t smaddr(const void* p) {
    return (uint32_t)__cvta_generic_to_shared(p);
}
#define CP16(dst, src) \
    asm volatile("cp.async.cg.shared.global [%0], [%1], 16;" :: "r"(dst), "l"(src))
#define CP_COMMIT() asm volatile("cp.async.commit_group;")
#define CP_WAIT(n)  asm volatile("cp.async.wait_group %0;" :: "n"(n))

// ldmatrix x4: 4 8x8-b16 matrices = tf32 fragment loads (thread t -> (t>>2, t&3))
#define LDSM4(r, addr) \
    asm volatile("ldmatrix.sync.aligned.m8n8.x4.shared.b16 {%0,%1,%2,%3}, [%4];" \
                 : "=r"((r)[0]), "=r"((r)[1]), "=r"((r)[2]), "=r"((r)[3]) \
                 : "r"(addr))

// ---------------------------------------------------------------------------
// Pre-pass kernels
// ---------------------------------------------------------------------------
__global__ void round_kernel(const float4* __restrict__ src, float4* __restrict__ dst, int n4) {
    int i = blockIdx.x * blockDim.x + threadIdx.x;
    if (i < n4) {
        float4 t = src[i];
        t.x = rtf(t.x); t.y = rtf(t.y); t.z = rtf(t.z); t.w = rtf(t.w);
        dst[i] = t;
    }
}

// src [K][N] row-major -> dst [N][K] row-major, tf32-rounded
__global__ void transpose_round_kernel(const float* __restrict__ src, float* __restrict__ dst,
                                       int K, int N) {
    __shared__ float t[32][33];
    int k0 = blockIdx.y * 32, n0 = blockIdx.x * 32;
    int tx = threadIdx.x, ty = threadIdx.y;  // 32 x 8
#pragma unroll
    for (int i = 0; i < 32; i += 8)
        t[ty + i][tx] = src[(size_t)(k0 + ty + i) * N + n0 + tx];
    __syncthreads();
#pragma unroll
    for (int i = 0; i < 32; i += 8)
        dst[(size_t)(n0 + ty + i) * K + k0 + tx] = rtf(t[tx][ty + i]);
}

// ---------------------------------------------------------------------------
// TF32 GEMM: C[M,N] = A[M,K] @ BT[N,K]^T (+epilogue). BM=BN=128, BK=32,
// 256 thr (8 warps 2m x 4n), warp tile 64x32. All fragments via ldmatrix.
// As/Bs stride 36 words -> every 8-row LDSM phase hits banks 4r (conflict-free).
// ---------------------------------------------------------------------------
struct GemmSmem {
    float As[3][128][36];
    float Bs[3][128][36];   // BT tile: rows = n, cols = k
};
#define GEMM_SMEM ((int)sizeof(GemmSmem))

template <bool HAS_BIAS, bool ROUND_OUT, bool SCALE_Q>
__global__ __launch_bounds__(256, 2) void gemm_tf32(
    const float* __restrict__ A, const float* __restrict__ BT,
    const float* __restrict__ bias, float* __restrict__ C,
    int M, int N, int K)
{
    extern __shared__ uint8_t smraw[];
    GemmSmem& S = *reinterpret_cast<GemmSmem*>(smraw);

    const int tid = threadIdx.x, lane = tid & 31, wid = tid >> 5;
    const int l4 = lane & 3, l2 = lane >> 2;
    const int wm = (wid & 1) * 64, wn = (wid >> 1) * 32;
    const int rowBase = blockIdx.y * 128, colBase = blockIdx.x * 128;

    // ldmatrix per-thread source coords
    const int la_r = (lane & 7) + ((lane >> 3) & 1) * 8;   // A rows (m0/m1 pairs)
    const int la_c = (lane >> 4) << 2;                     // A col half
    const int lb_r = (lane & 7) + ((lane >> 4) << 3);      // B rows (m2/m3 -> +8)
    const int lb_c = ((lane >> 3) & 1) << 2;               // B col half

    const float* Ag = A + (size_t)rowBase * K;
    const float* Bg = BT + (size_t)colBase * K;

    float acc[4][4][4];
#pragma unroll
    for (int mt = 0; mt < 4; mt++)
#pragma unroll
        for (int nt = 0; nt < 4; nt++)
#pragma unroll
            for (int i = 0; i < 4; i++) acc[mt][nt][i] = 0.f;

    auto issue = [&](int s, int k0) {
#pragma unroll
        for (int i = 0; i < 4; i++) {              // A tile 128x32
            int c = tid + 256 * i;
            int row = c >> 3, cc = (c & 7) << 2;
            CP16(smaddr(&S.As[s][row][cc]), Ag + (size_t)row * K + k0 + cc);
        }
#pragma unroll
        for (int i = 0; i < 4; i++) {              // BT tile 128x32
            int c = tid + 256 * i;
            int row = c >> 3, cc = (c & 7) << 2;
            CP16(smaddr(&S.Bs[s][row][cc]), Bg + (size_t)row * K + k0 + cc);
        }
        CP_COMMIT();
    };

    const int nIter = K >> 5;
    issue(0, 0);
    if (nIter > 1) issue(1, 32);

    for (int it = 0; it < nIter; it++) {
        if (it + 1 < nIter) { CP_WAIT(1); } else { CP_WAIT(0); }
        __syncthreads();
        if (it + 2 < nIter) issue((it + 2) % 3, (it + 2) << 5);
        const int buf = it % 3;

#pragma unroll
        for (int ks = 0; ks < 32; ks += 8) {
            uint32_t af[4][4], bf[2][4];
#pragma unroll
            for (int mt = 0; mt < 4; mt++)
                LDSM4(af[mt], smaddr(&S.As[buf][wm + 16 * mt + la_r][ks + la_c]));
#pragma unroll
            for (int j = 0; j < 2; j++)
                LDSM4(bf[j], smaddr(&S.Bs[buf][wn + 16 * j + lb_r][ks + lb_c]));
#pragma unroll
            for (int mt = 0; mt < 4; mt++)
#pragma unroll
                for (int nt = 0; nt < 4; nt++)
                    mma8(acc[mt][nt], af[mt], &bf[nt >> 1][(nt & 1) * 2]);
        }
    }

#pragma unroll
    for (int mt = 0; mt < 4; mt++) {
        int row = rowBase + wm + mt * 16 + l2;
#pragma unroll
        for (int nt = 0; nt < 4; nt++) {
            int col = colBase + wn + nt * 8 + 2 * l4;
            float sc = 1.f;
            if (SCALE_Q) sc = (col < 1024) ? 0.125f : 1.f;
            float bx = 0.f, by = 0.f;
            if (HAS_BIAS) { bx = bias[col]; by = bias[col + 1]; }
            float2 v0, v1;
            v0.x = acc[mt][nt][0] * sc + bx;  v0.y = acc[mt][nt][1] * sc + by;
            v1.x = acc[mt][nt][2] * sc + bx;  v1.y = acc[mt][nt][3] * sc + by;
            if (ROUND_OUT) {
                v0.x = rtf(v0.x); v0.y = rtf(v0.y);
                v1.x = rtf(v1.x); v1.y = rtf(v1.y);
            }
            *(float2*)(C + (size_t)row * N + col) = v0;
            *(float2*)(C + (size_t)(row + 8) * N + col) = v1;
        }
    }
}

// ---------------------------------------------------------------------------
// Flash attention: tf32 mma, 2-stage cp.async K/V, NO P smem (shuffle-based
// A-fragment exchange), Q/K fragments via ldmatrix. smem = 104 KB -> 2 CTAs/SM.
// Block = (q-tile 128, one (b,h)); 8 warps x 16 q-rows, full kv width 64.
// ---------------------------------------------------------------------------
struct FlashSmem {
    float Qs[128][68];
    float Ks[2][64][68];
    float Vs[2][64][72];
};
#define FLASH_SMEM ((int)sizeof(FlashSmem))

__global__ __launch_bounds__(256, 2) void flash_tf32()
{
    extern __shared__ uint8_t smraw[];
    FlashSmem& S = *reinterpret_cast<FlashSmem*>(smraw);

    const int tid = threadIdx.x, lane = tid & 31, wid = tid >> 5;
    const int l4 = lane & 3, l2 = lane >> 2;
    const int qt = blockIdx.x;            // 0..15
    const int bh = blockIdx.y;            // 0..31
    const int b = bh >> 4, h = bh & 15;
    const int rowb = wid * 16;

    // ldmatrix per-thread coords
    const int la_r = (lane & 7) + ((lane >> 3) & 1) * 8;   // Q (A-operand)
    const int la_c = (lane >> 4) << 2;
    const int lb_r = (lane & 7) + ((lane >> 4) << 3);      // K (B-operand)
    const int lb_c = ((lane >> 3) & 1) << 2;

    const float* Qg = g_qkv + (size_t)b * 2048 * 3072 + (size_t)h * 64;
    const float* Kg = Qg + 1024;
    const float* Vg = Qg + 2048;

    auto issueKV = [&](int s, int kt) {
#pragma unroll
        for (int i = 0; i < 4; i++) {
            int c = tid + 256 * i;
            int r = c >> 4, cc = (c & 15) << 2;
            CP16(smaddr(&S.Ks[s][r][cc]), Kg + (size_t)(kt * 64 + r) * 3072 + cc);
        }
#pragma unroll
        for (int i = 0; i < 4; i++) {
            int c = tid + 256 * i;
            int r = c >> 4, cc = (c & 15) << 2;
            CP16(smaddr(&S.Vs[s][r][cc]), Vg + (size_t)(kt * 64 + r) * 3072 + cc);
        }
        CP_COMMIT();
    };

    // prologue: Q + KV0 as one group
#pragma unroll
    for (int i = 0; i < 8; i++) {
        int c = tid + 256 * i;
        int r = c >> 4, cc = (c & 15) << 2;
        CP16(smaddr(&S.Qs[r][cc]), Qg + (size_t)(qt * 128 + r) * 3072 + cc);
    }
    issueKV(0, 0);

    float o[8][4];
    float m[2] = {-1e30f, -1e30f}, l[2] = {0.f, 0.f};
#pragma unroll
    for (int nt = 0; nt < 8; nt++)
#pragma unroll
        for (int i = 0; i < 4; i++) o[nt][i] = 0.f;

    for (int kt = 0; kt < 32; kt++) {
        CP_WAIT(0);                  // tile kt landed (issued one tile ago)
        __syncthreads();             // visibility + all warps done with buf^1
        if (kt + 1 < 32) issueKV((kt + 1) & 1, kt + 1);
        const int buf = kt & 1;

        // ---- S = Q @ K^T : 16 x 64 per warp, k = 64 (Q pre-scaled 1/8) ----
        float s[8][4];
#pragma unroll
        for (int nt = 0; nt < 8; nt++)
#pragma unroll
            for (int i = 0; i < 4; i++) s[nt][i] = 0.f;
#pragma unroll
        for (int ks = 0; ks < 64; ks += 8) {
            uint32_t a[4], bk[4][4];
            LDSM4(a, smaddr(&S.Qs[rowb + la_r][ks + la_c]));
#pragma unroll
            for (int j = 0; j < 4; j++)
                LDSM4(bk[j], smaddr(&S.Ks[buf][16 * j + lb_r][ks + lb_c]));
#pragma unroll
            for (int nt = 0; nt < 8; nt++)
                mma8(s[nt], a, &bk[nt >> 1][(nt & 1) * 2]);
        }

        // ---- online softmax (width-4 shuffle segments) ----
#pragma unroll
        for (int rr = 0; rr < 2; rr++) {
            float mloc = -1e30f;
#pragma unroll
            for (int nt = 0; nt < 8; nt++)
                mloc = fmaxf(mloc, fmaxf(s[nt][2 * rr], s[nt][2 * rr + 1]));
            mloc = fmaxf(mloc, __shfl_xor_sync(0xffffffffu, mloc, 1, 4));
            mloc = fmaxf(mloc, __shfl_xor_sync(0xffffffffu, mloc, 2, 4));
            float mn = fmaxf(m[rr], mloc);
            float fac = __expf(m[rr] - mn);
            m[rr] = mn;
            float lloc = 0.f;
#pragma unroll
            for (int nt = 0; nt < 8; nt++) {
                s[nt][2 * rr]     = __expf(s[nt][2 * rr] - mn);
                s[nt][2 * rr + 1] = __expf(s[nt][2 * rr + 1] - mn);
                lloc += s[nt][2 * rr] + s[nt][2 * rr + 1];
            }
            lloc += __shfl_xor_sync(0xffffffffu, lloc, 1, 4);
            lloc += __shfl_xor_sync(0xffffffffu, lloc, 2, 4);
            l[rr] = l[rr] * fac + lloc;
#pragma unroll
            for (int nt = 0; nt < 8; nt++) {
                o[nt][2 * rr]     *= fac;
                o[nt][2 * rr + 1] *= fac;
            }
        }

        // round P to tf32 grid (same rounding point as before)
#pragma unroll
        for (int nt = 0; nt < 8; nt++)
#pragma unroll
            for (int e = 0; e < 4; e++) s[nt][e] = rtf(s[nt][e]);

        // ---- O += P @ V : P A-fragments via width-4 shuffles (no smem) ----
        // P[row][col]: row = l2 + 8*(e>>1), col = 8*nt + 2*l4 + (e&1)
        // a0 = P[l2][ks+l4] lives in lane (lane&~3)|(l4>>1), reg s[ks>>3][l4&1]
        const int L = (lane & 0x1C) | (l4 >> 1);
        const bool odd = l4 & 1;
#pragma unroll
        for (int ks = 0; ks < 64; ks += 8) {
            const int nts = ks >> 3;
            float e0 = __shfl_sync(0xffffffffu, s[nts][0], L);
            float e1 = __shfl_sync(0xffffffffu, s[nts][1], L);
            float e2 = __shfl_sync(0xffffffffu, s[nts][2], L);
            float e3 = __shfl_sync(0xffffffffu, s[nts][3], L);
            float f0 = __shfl_sync(0xffffffffu, s[nts][0], L + 2);
            float f1 = __shfl_sync(0xffffffffu, s[nts][1], L + 2);
            float f2 = __shfl_sync(0xffffffffu, s[nts][2], L + 2);
            float f3 = __shfl_sync(0xffffffffu, s[nts][3], L + 2);
            uint32_t a[4];
            a[0] = fbits(odd ? e1 : e0);   // P[l2][ks+l4]
            a[1] = fbits(odd ? e3 : e2);   // P[l2+8][ks+l4]
            a[2] = fbits(odd ? f1 : f0);   // P[l2][ks+l4+4]
            a[3] = fbits(odd ? f3 : f2);   // P[l2+8][ks+l4+4]
#pragma unroll
            for (int nt = 0; nt < 8; nt++) {
                uint32_t bv[2] = {fbits(S.Vs[buf][ks + l4][nt * 8 + l2]),
                                  fbits(S.Vs[buf][ks + l4 + 4][nt * 8 + l2])};
                mma8(o[nt], a, bv);
            }
        }
    }

    // epilogue (rounded so proj GEMM consumes tf32-valid data)
    const float inv0 = 1.f / l[0], inv1 = 1.f / l[1];
    float* Og = g_att + ((size_t)b * 2048 + (size_t)qt * 128) * 1024 + (size_t)h * 64;
    const int r0 = rowb + l2;
#pragma unroll
    for (int nt = 0; nt < 8; nt++) {
        int col = nt * 8 + 2 * l4;
        float2 v0 = make_float2(rtf(o[nt][0] * inv0), rtf(o[nt][1] * inv0));
        *(float2*)(Og + (size_t)r0 * 1024 + col) = v0;
        float2 v1 = make_float2(rtf(o[nt][2] * inv1), rtf(o[nt][3] * inv1));
        *(float2*)(Og + (size_t)(r0 + 8) * 1024 + col) = v1;
    }
}

// ---------------------------------------------------------------------------
extern "C" void kernel_launch(void* const* d_in, const int* in_sizes, int n_in,
                              void* d_out, int out_size)
{
    const float* x      = (const float*)d_in[0];   // [2,2048,1024]
    const float* w_qkv  = (const float*)d_in[1];   // [1024,3072]
    const float* w_proj = (const float*)d_in[2];   // [1024,1024]
    const float* b_proj = (const float*)d_in[3];   // [1024]
    float* out = (float*)d_out;                    // [2,2048,1024]

    float *qkv, *att, *xr, *wqkvT, *wprojT;
    cudaGetSymbolAddress((void**)&qkv, g_qkv);
    cudaGetSymbolAddress((void**)&att, g_att);
    cudaGetSymbolAddress((void**)&xr, g_xr);
    cudaGetSymbolAddress((void**)&wqkvT, g_wqkvT);
    cudaGetSymbolAddress((void**)&wprojT, g_wprojT);

    // 0) pre-pass: round x; transpose+round weights to [N][K]
    round_kernel<<<(4096 * 1024 / 4 + 255) / 256, 256>>>(
        (const float4*)x, (float4*)xr, 4096 * 1024 / 4);
    transpose_round_kernel<<<dim3(QKV_N / 32, CC / 32), dim3(32, 8)>>>(
        w_qkv, wqkvT, CC, QKV_N);
    transpose_round_kernel<<<dim3(CC / 32, CC / 32), dim3(32, 8)>>>(
        w_proj, wprojT, CC, CC);

    // 1) QKV projection (epilogue: q *= 1/8, round tf32)
    cudaFuncSetAttribute((const void*)gemm_tf32<false, true, true>,
                         cudaFuncAttributeMaxDynamicSharedMemorySize, GEMM_SMEM);
    gemm_tf32<false, true, true><<<dim3(QKV_N / 128, M_ROWS / 128), 256, GEMM_SMEM>>>(
        xr, wqkvT, nullptr, qkv, M_ROWS, QKV_N, CC);

    // 2) Flash attention (2 CTAs/SM)
    cudaFuncSetAttribute(flash_tf32,
                         cudaFuncAttributeMaxDynamicSharedMemorySize, FLASH_SMEM);
    flash_tf32<<<dim3(16, 32), 256, FLASH_SMEM>>>();

    // 3) Output projection + bias (fp32 out)
    cudaFuncSetAttribute((const void*)gemm_tf32<true, false, false>,
                         cudaFuncAttributeMaxDynamicSharedMemorySize, GEMM_SMEM);
    gemm_tf32<true, false, false><<<dim3(CC / 128, M_ROWS / 128), 256, GEMM_SMEM>>>(
        att, wprojT, b_proj, out, M_ROWS, CC, CC);
}

// round 15
// speedup vs baseline: 2.0281x; 1.7538x over previous
#include <cuda_runtime.h>
#include <cuda_fp16.h>
#include <math.h>
#include <stdint.h>

// Problem: B=2, N=2048, C=1024, H=16, D=64, SCALE=1/8
#define M_ROWS 4096
#define QKV_N  3072
#define CC     1024

// Scratch (device globals: allocation-guard-safe)
__device__ __half g_qkvh[4096 * 3072];    // [B*N, 3C] fp16, q pre-scaled
__device__ __half g_atth[4096 * 1024];    // [B*N, C] fp16 attention out
__device__ __half g_xh[4096 * 1024];      // fp16 x
__device__ __half g_wqkvTh[3072 * 1024];  // fp16 w_qkv^T  [N][K]
__device__ __half g_wprojTh[1024 * 1024]; // fp16 w_proj^T [N][K]

// ---------------------------------------------------------------------------
// helpers
// ---------------------------------------------------------------------------
__device__ __forceinline__ uint32_t h2pack(float lo, float hi) {
    __half2 h = __floats2half2_rn(lo, hi);
    return *(uint32_t*)&h;
}

__device__ __forceinline__ void mma16(float* d, const uint32_t* a, const uint32_t* b) {
    asm volatile(
        "mma.sync.aligned.m16n8k16.row.col.f32.f16.f16.f32 "
        "{%0,%1,%2,%3}, {%4,%5,%6,%7}, {%8,%9}, {%0,%1,%2,%3};"
        : "+f"(d[0]), "+f"(d[1]), "+f"(d[2]), "+f"(d[3])
        : "r"(a[0]), "r"(a[1]), "r"(a[2]), "r"(a[3]), "r"(b[0]), "r"(b[1]));
}

__device__ __forceinline__ uint32_t smaddr(const void* p) {
    return (uint32_t)__cvta_generic_to_shared(p);
}
#define CP16(dst, src) \
    asm volatile("cp.async.cg.shared.global [%0], [%1], 16;" :: "r"(dst), "l"(src))
#define CP_COMMIT() asm volatile("cp.async.commit_group;")
#define CP_WAIT(n)  asm volatile("cp.async.wait_group %0;" :: "n"(n))

#define LDSM4(r, addr) \
    asm volatile("ldmatrix.sync.aligned.m8n8.x4.shared.b16 {%0,%1,%2,%3}, [%4];" \
                 : "=r"((r)[0]), "=r"((r)[1]), "=r"((r)[2]), "=r"((r)[3]) \
                 : "r"(addr))
#define LDSM4T(r, addr) \
    asm volatile("ldmatrix.sync.aligned.m8n8.x4.trans.shared.b16 {%0,%1,%2,%3}, [%4];" \
                 : "=r"((r)[0]), "=r"((r)[1]), "=r"((r)[2]), "=r"((r)[3]) \
                 : "r"(addr))

// ---------------------------------------------------------------------------
// Pre-pass: fp32 -> fp16
// ---------------------------------------------------------------------------
__global__ void tohalf_kernel(const float4* __restrict__ src, __half2* __restrict__ dst, int n4) {
    int i = blockIdx.x * blockDim.x + threadIdx.x;
    if (i < n4) {
        float4 t = src[i];
        dst[2 * i]     = __floats2half2_rn(t.x, t.y);
        dst[2 * i + 1] = __floats2half2_rn(t.z, t.w);
    }
}

// src [K][N] f32 row-major -> dst [N][K] fp16 row-major
__global__ void transpose_half_kernel(const float* __restrict__ src, __half* __restrict__ dst,
                                      int K, int N) {
    __shared__ float t[32][33];
    int k0 = blockIdx.y * 32, n0 = blockIdx.x * 32;
    int tx = threadIdx.x, ty = threadIdx.y;  // 32 x 8
#pragma unroll
    for (int i = 0; i < 32; i += 8)
        t[ty + i][tx] = src[(size_t)(k0 + ty + i) * N + n0 + tx];
    __syncthreads();
#pragma unroll
    for (int i = 0; i < 32; i += 8)
        dst[(size_t)(n0 + ty + i) * K + k0 + tx] = __float2half_rn(t[tx][ty + i]);
}

// ---------------------------------------------------------------------------
// FP16 GEMM: C[M,N] = A[M,K] @ BT[N,K]^T (+epilogue). BM=BN=128, BK=32,
// 256 thr (8 warps 2m x 4n), warp tile 64x32, m16n8k16. 3-stage cp.async.
// smem rows stride 40 halfs (80B) -> ldmatrix conflict-free.
// OUT_HALF=1: C is __half, q-cols scaled 1/8 (QKV). OUT_HALF=0: f32 + bias.
// ---------------------------------------------------------------------------
struct GemmSmem {
    __half As[3][128][40];
    __half Bs[3][128][40];
};
#define GEMM_SMEM ((int)sizeof(GemmSmem))

template <bool OUT_HALF>
__global__ __launch_bounds__(256, 2) void gemm_fp16(
    const __half* __restrict__ A, const __half* __restrict__ BT,
    const float* __restrict__ bias, void* __restrict__ Cv,
    int M, int N, int K)
{
    extern __shared__ uint8_t smraw[];
    GemmSmem& S = *reinterpret_cast<GemmSmem*>(smraw);

    const int tid = threadIdx.x, lane = tid & 31, wid = tid >> 5;
    const int l4 = lane & 3, l2 = lane >> 2;
    const int wm = (wid & 1) * 64, wn = (wid >> 1) * 32;
    const int rowBase = blockIdx.y * 128, colBase = blockIdx.x * 128;

    // ldmatrix per-thread coords (b16 units)
    const int la_r = (lane & 7) + ((lane >> 3) & 1) * 8;   // A / m16k16
    const int la_c = (lane >> 4) << 3;
    const int lb_n = (lane & 7) + ((lane >> 4) << 3);      // B / n16k16
    const int lb_c = ((lane >> 3) & 1) << 3;

    const __half* Ag = A + (size_t)rowBase * K;
    const __half* Bg = BT + (size_t)colBase * K;

    float acc[4][4][4];
#pragma unroll
    for (int mt = 0; mt < 4; mt++)
#pragma unroll
        for (int nt = 0; nt < 4; nt++)
#pragma unroll
            for (int i = 0; i < 4; i++) acc[mt][nt][i] = 0.f;

    auto issue = [&](int s, int k0) {
#pragma unroll
        for (int i = 0; i < 2; i++) {              // A tile 128x32 halfs (64B/row)
            int c = tid + 256 * i;
            int row = c >> 2, ch = (c & 3) << 3;
            CP16(smaddr(&S.As[s][row][ch]), Ag + (size_t)row * K + k0 + ch);
        }
#pragma unroll
        for (int i = 0; i < 2; i++) {              // BT tile 128x32
            int c = tid + 256 * i;
            int row = c >> 2, ch = (c & 3) << 3;
            CP16(smaddr(&S.Bs[s][row][ch]), Bg + (size_t)row * K + k0 + ch);
        }
        CP_COMMIT();
    };

    const int nIter = K >> 5;
    issue(0, 0);
    if (nIter > 1) issue(1, 32);

    for (int it = 0; it < nIter; it++) {
        if (it + 1 < nIter) { CP_WAIT(1); } else { CP_WAIT(0); }
        __syncthreads();
        if (it + 2 < nIter) issue((it + 2) % 3, (it + 2) << 5);
        const int buf = it % 3;

#pragma unroll
        for (int ks = 0; ks < 32; ks += 16) {
            uint32_t af[4][4], bf[2][4];
#pragma unroll
            for (int mt = 0; mt < 4; mt++)
                LDSM4(af[mt], smaddr(&S.As[buf][wm + 16 * mt + la_r][ks + la_c]));
#pragma unroll
            for (int j = 0; j < 2; j++)
                LDSM4(bf[j], smaddr(&S.Bs[buf][wn + 16 * j + lb_n][ks + lb_c]));
#pragma unroll
            for (int mt = 0; mt < 4; mt++)
#pragma unroll
                for (int nt = 0; nt < 4; nt++)
                    mma16(acc[mt][nt], af[mt], &bf[nt >> 1][(nt & 1) * 2]);
        }
    }

#pragma unroll
    for (int mt = 0; mt < 4; mt++) {
        int row = rowBase + wm + mt * 16 + l2;
#pragma unroll
        for (int nt = 0; nt < 4; nt++) {
            int col = colBase + wn + nt * 8 + 2 * l4;
            if (OUT_HALF) {
                __half* C = (__half*)Cv;
                const float sc = (col < 1024) ? 0.125f : 1.f;   // q pre-scale
                *(__half2*)(C + (size_t)row * N + col) =
                    __floats2half2_rn(acc[mt][nt][0] * sc, acc[mt][nt][1] * sc);
                *(__half2*)(C + (size_t)(row + 8) * N + col) =
                    __floats2half2_rn(acc[mt][nt][2] * sc, acc[mt][nt][3] * sc);
            } else {
                float* C = (float*)Cv;
                const float bx = bias[col], by = bias[col + 1];
                *(float2*)(C + (size_t)row * N + col) =
                    make_float2(acc[mt][nt][0] + bx, acc[mt][nt][1] + by);
                *(float2*)(C + (size_t)(row + 8) * N + col) =
                    make_float2(acc[mt][nt][2] + bx, acc[mt][nt][3] + by);
            }
        }
    }
}

// ---------------------------------------------------------------------------
// Flash attention fp16: S C-fragment IS the PV A-fragment (FA2 layout) -> no
// P smem, no shuffles. 2-stage cp.async K/V. smem 54KB -> 2+ CTAs/SM.
// Block = (q-tile 128, one (b,h)); 8 warps x 16 q-rows, kv tile 64.
// ---------------------------------------------------------------------------
struct FlashSmem {
    __half Qs[128][72];
    __half Ks[2][64][72];
    __half Vs[2][64][72];
};
#define FLASH_SMEM ((int)sizeof(FlashSmem))

__global__ __launch_bounds__(256, 2) void flash_fp16()
{
    extern __shared__ uint8_t smraw[];
    FlashSmem& S = *reinterpret_cast<FlashSmem*>(smraw);

    const int tid = threadIdx.x, lane = tid & 31, wid = tid >> 5;
    const int l4 = lane & 3, l2 = lane >> 2;
    const int qt = blockIdx.x;            // 0..15
    const int bh = blockIdx.y;            // 0..31
    const int b = bh >> 4, h = bh & 15;
    const int rowb = wid * 16;

    const int la_r = (lane & 7) + ((lane >> 3) & 1) * 8;   // A rows / V-trans rows
    const int la_c = (lane >> 4) << 3;                     // col half (b16)
    const int lb_n = (lane & 7) + ((lane >> 4) << 3);      // B n rows
    const int lb_c = ((lane >> 3) & 1) << 3;

    const __half* Qg = g_qkvh + (size_t)b * 2048 * 3072 + (size_t)h * 64;
    const __half* Kg = Qg + 1024;
    const __half* Vg = Qg + 2048;

    auto issueKV = [&](int s, int kt) {
#pragma unroll
        for (int i = 0; i < 2; i++) {     // K 64x64 halfs = 512 16B chunks
            int c = tid + 256 * i;
            int r = c >> 3, ch = (c & 7) << 3;
            CP16(smaddr(&S.Ks[s][r][ch]), Kg + (size_t)(kt * 64 + r) * 3072 + ch);
        }
#pragma unroll
        for (int i = 0; i < 2; i++) {
            int c = tid + 256 * i;
            int r = c >> 3, ch = (c & 7) << 3;
            CP16(smaddr(&S.Vs[s][r][ch]), Vg + (size_t)(kt * 64 + r) * 3072 + ch);
        }
        CP_COMMIT();
    };

    // prologue: Q + KV0 as one group
#pragma unroll
    for (int i = 0; i < 4; i++) {
        int c = tid + 256 * i;
        int r = c >> 3, ch = (c & 7) << 3;
        CP16(smaddr(&S.Qs[r][ch]), Qg + (size_t)(qt * 128 + r) * 3072 + ch);
    }
    issueKV(0, 0);

    float o[8][4];
    float m[2] = {-1e30f, -1e30f}, l[2] = {0.f, 0.f};
#pragma unroll
    for (int nt = 0; nt < 8; nt++)
#pragma unroll
        for (int i = 0; i < 4; i++) o[nt][i] = 0.f;

    for (int kt = 0; kt < 32; kt++) {
        CP_WAIT(0);
        __syncthreads();
        if (kt + 1 < 32) issueKV((kt + 1) & 1, kt + 1);
        const int buf = kt & 1;

        // ---- S = Q @ K^T : 16 x 64 per warp, k = 64 (Q pre-scaled) ----
        float s[8][4];
#pragma unroll
        for (int nt = 0; nt < 8; nt++)
#pragma unroll
            for (int i = 0; i < 4; i++) s[nt][i] = 0.f;
#pragma unroll
        for (int ks = 0; ks < 64; ks += 16) {
            uint32_t a[4], bk[4][4];
            LDSM4(a, smaddr(&S.Qs[rowb + la_r][ks + la_c]));
#pragma unroll
            for (int j = 0; j < 4; j++)
                LDSM4(bk[j], smaddr(&S.Ks[buf][16 * j + lb_n][ks + lb_c]));
#pragma unroll
            for (int nt = 0; nt < 8; nt++)
                mma16(s[nt], a, &bk[nt >> 1][(nt & 1) * 2]);
        }

        // ---- online softmax (width-4 shuffle segments) ----
#pragma unroll
        for (int rr = 0; rr < 2; rr++) {
            float mloc = -1e30f;
#pragma unroll
            for (int nt = 0; nt < 8; nt++)
                mloc = fmaxf(mloc, fmaxf(s[nt][2 * rr], s[nt][2 * rr + 1]));
            mloc = fmaxf(mloc, __shfl_xor_sync(0xffffffffu, mloc, 1, 4));
            mloc = fmaxf(mloc, __shfl_xor_sync(0xffffffffu, mloc, 2, 4));
            float mn = fmaxf(m[rr], mloc);
            float fac = __expf(m[rr] - mn);
            m[rr] = mn;
            float lloc = 0.f;
#pragma unroll
            for (int nt = 0; nt < 8; nt++) {
                s[nt][2 * rr]     = __expf(s[nt][2 * rr] - mn);
                s[nt][2 * rr + 1] = __expf(s[nt][2 * rr + 1] - mn);
                lloc += s[nt][2 * rr] + s[nt][2 * rr + 1];
            }
            lloc += __shfl_xor_sync(0xffffffffu, lloc, 1, 4);
            lloc += __shfl_xor_sync(0xffffffffu, lloc, 2, 4);
            l[rr] = l[rr] * fac + lloc;
#pragma unroll
            for (int nt = 0; nt < 8; nt++) {
                o[nt][2 * rr]     *= fac;
                o[nt][2 * rr + 1] *= fac;
            }
        }

        // ---- O += P @ V : P = S C-fragment repacked to fp16 A-fragment ----
#pragma unroll
        for (int j = 0; j < 4; j++) {              // kv blocks of 16
            uint32_t a[4];
            a[0] = h2pack(s[2 * j][0],     s[2 * j][1]);
            a[1] = h2pack(s[2 * j][2],     s[2 * j][3]);
            a[2] = h2pack(s[2 * j + 1][0], s[2 * j + 1][1]);
            a[3] = h2pack(s[2 * j + 1][2], s[2 * j + 1][3]);
            uint32_t bv[4][4];
#pragma unroll
            for (int c = 0; c < 4; c++)            // d chunks of 16
                LDSM4T(bv[c], smaddr(&S.Vs[buf][16 * j + la_r][16 * c + la_c]));
#pragma unroll
            for (int nt = 0; nt < 8; nt++)
                mma16(o[nt], a, &bv[nt >> 1][(nt & 1) * 2]);
        }
    }

    // epilogue -> fp16 att buffer
    const float inv0 = 1.f / l[0], inv1 = 1.f / l[1];
    __half* Og = g_atth + ((size_t)b * 2048 + (size_t)qt * 128) * 1024 + (size_t)h * 64;
    const int r0 = rowb + l2;
#pragma unroll
    for (int nt = 0; nt < 8; nt++) {
        int col = nt * 8 + 2 * l4;
        *(__half2*)(Og + (size_t)r0 * 1024 + col) =
            __floats2half2_rn(o[nt][0] * inv0, o[nt][1] * inv0);
        *(__half2*)(Og + (size_t)(r0 + 8) * 1024 + col) =
            __floats2half2_rn(o[nt][2] * inv1, o[nt][3] * inv1);
    }
}

// ---------------------------------------------------------------------------
extern "C" void kernel_launch(void* const* d_in, const int* in_sizes, int n_in,
                              void* d_out, int out_size)
{
    const float* x      = (const float*)d_in[0];   // [2,2048,1024]
    const float* w_qkv  = (const float*)d_in[1];   // [1024,3072]
    const float* w_proj = (const float*)d_in[2];   // [1024,1024]
    const float* b_proj = (const float*)d_in[3];   // [1024]
    float* out = (float*)d_out;                    // [2,2048,1024]

    __half *qkv, *att, *xh, *wqkvT, *wprojT;
    cudaGetSymbolAddress((void**)&qkv, g_qkvh);
    cudaGetSymbolAddress((void**)&att, g_atth);
    cudaGetSymbolAddress((void**)&xh, g_xh);
    cudaGetSymbolAddress((void**)&wqkvT, g_wqkvTh);
    cudaGetSymbolAddress((void**)&wprojT, g_wprojTh);

    // 0) pre-pass: x -> fp16; weights -> transposed fp16 [N][K]
    tohalf_kernel<<<(4096 * 1024 / 4 + 255) / 256, 256>>>(
        (const float4*)x, (__half2*)xh, 4096 * 1024 / 4);
    transpose_half_kernel<<<dim3(QKV_N / 32, CC / 32), dim3(32, 8)>>>(
        w_qkv, wqkvT, CC, QKV_N);
    transpose_half_kernel<<<dim3(CC / 32, CC / 32), dim3(32, 8)>>>(
        w_proj, wprojT, CC, CC);

    // 1) QKV projection (fp16 out, q scaled 1/8)
    cudaFuncSetAttribute((const void*)gemm_fp16<true>,
                         cudaFuncAttributeMaxDynamicSharedMemorySize, GEMM_SMEM);
    gemm_fp16<true><<<dim3(QKV_N / 128, M_ROWS / 128), 256, GEMM_SMEM>>>(
        xh, wqkvT, nullptr, qkv, M_ROWS, QKV_N, CC);

    // 2) Flash attention
    cudaFuncSetAttribute(flash_fp16,
                         cudaFuncAttributeMaxDynamicSharedMemorySize, FLASH_SMEM);
    flash_fp16<<<dim3(16, 32), 256, FLASH_SMEM>>>();

    // 3) Output projection + bias (fp32 out)
    cudaFuncSetAttribute((const void*)gemm_fp16<false>,
                         cudaFuncAttributeMaxDynamicSharedMemorySize, GEMM_SMEM);
    gemm_fp16<false><<<dim3(CC / 128, M_ROWS / 128), 256, GEMM_SMEM>>>(
        att, wprojT, b_proj, out, M_ROWS, CC, CC);
}